// round 6
// baseline (speedup 1.0000x reference)
#include <cuda_runtime.h>
#include <stdint.h>
#include <stdlib.h>

// ---------------------------------------------------------------------------
// GCN 2-layer forward, N=100k, E=1.6M, d=64. Restructured to minimize scratch:
//   agg1 = A (x . rout)            [A includes self loops]  -> g_acc (25.6MB)
//   a1   = relu(rin . agg1 @ W1 + b1)
//   q    = (rout . a1) . (W2@Wr)   [scalar per node, GEMM epilogue]
//   out  = rin . (A q) + (b2.Wr + br)   [scalar scatter into d_out]
// Total device-global scratch ~27MB (vs 52MB before) to stay under the
// harness's module-load allowance (prior rounds: 128MB arena flagged).
// ---------------------------------------------------------------------------

#define MAXN 100352
#define D 64

__device__ float g_acc[MAXN * D];   // layer-1 aggregation accumulator
__device__ float g_q[MAXN];         // per-node scalar for layer 2
__device__ float g_rout[MAXN];
__device__ float g_rin[MAXN];
__device__ float g_w2r[D];          // W2 @ Wr
__device__ float g_c;               // b2 . Wr + br
__device__ int   g_stride;          // 1 = indices are int32; 2 = int64 (low word)

// Default-priority constructor (allowed): ask driver for eager module loading.
__attribute__((constructor))
static void _eager_modules() { setenv("CUDA_MODULE_LOADING", "EAGER", 1); }

// ------------------------- index dtype detection ----------------------------
// int64 little-endian with values < 2^31 has all-zero high words at odd
// 32-bit positions; int32 data there is ~random nonzero. Deterministic.
__global__ void k_detect(const unsigned* __restrict__ src, int e) {
    __shared__ int nz;
    if (threadIdx.x == 0) nz = 0;
    __syncthreads();
    int words = min(e, 4096);
    for (int i = threadIdx.x; i < words; i += blockDim.x)
        if (src[2 * i + 1] != 0u) { nz = 1; break; }
    __syncthreads();
    if (threadIdx.x == 0) g_stride = nz ? 1 : 2;
}

__device__ __forceinline__ int load_idx(const int* p, int t, int st, int n) {
    int v = p[(size_t)t * st];
    return min(max(v, 0), n - 1);
}

// ------------------------------ degrees -------------------------------------

__global__ void k_deg_init(int n) {
    int i = blockIdx.x * blockDim.x + threadIdx.x;
    if (i < n) { g_rout[i] = 1.0f; g_rin[i] = 1.0f; }   // self-loop
}

__global__ void k_deg(const int* __restrict__ src, const int* __restrict__ dst,
                      int e, int n) {
    int t = blockIdx.x * blockDim.x + threadIdx.x;
    if (t >= e) return;
    int st = g_stride;
    atomicAdd(&g_rout[load_idx(src, t, st, n)], 1.0f);
    atomicAdd(&g_rin[load_idx(dst, t, st, n)], 1.0f);
}

__global__ void k_rsqrt(int n) {
    int i = blockIdx.x * blockDim.x + threadIdx.x;
    if (i < n) {
        g_rout[i] = rsqrtf(g_rout[i]);
        g_rin[i]  = rsqrtf(g_rin[i]);
    }
}

// --------------------- layer-1 accumulator init + scatter -------------------
// init: g_acc[i] = x[i] * rout[i]  (self-loop term)
__global__ void k_init_acc(const float4* __restrict__ x4, int n) {
    int i = blockIdx.x * blockDim.x + threadIdx.x;        // n*16 float4's
    if (i >= n * (D / 4)) return;
    int row = i >> 4;
    float r = g_rout[row];
    float4 v = x4[i];
    v.x *= r; v.y *= r; v.z *= r; v.w *= r;
    ((float4*)g_acc)[i] = v;
}

// 16 lanes per edge, 16B per lane, gather from input x, red.add into g_acc.
__global__ void k_scatter1(const float* __restrict__ x,
                           const int* __restrict__ src,
                           const int* __restrict__ dst, int e, int n) {
    int gt = blockIdx.x * blockDim.x + threadIdx.x;
    int ed = gt >> 4;
    if (ed >= e) return;
    int lane = gt & 15;
    int st = g_stride;
    int s = load_idx(src, ed, st, n);
    int d = load_idx(dst, ed, st, n);
    float r = g_rout[s];
    float4 v = ((const float4*)(x + (size_t)s * D))[lane];
    v.x *= r; v.y *= r; v.z *= r; v.w *= r;
    float* dp = g_acc + (size_t)d * D + lane * 4;
    asm volatile("red.global.add.v4.f32 [%0], {%1,%2,%3,%4};"
                 :: "l"(dp), "f"(v.x), "f"(v.y), "f"(v.z), "f"(v.w)
                 : "memory");
}

// ------------------------- W2@Wr precompute ---------------------------------
__global__ void k_w2r(const float* __restrict__ W2, const float* __restrict__ b2,
                      const float* __restrict__ Wr, const float* __restrict__ br) {
    int k = threadIdx.x;          // 64 threads
    float s = 0.f;
#pragma unroll
    for (int j = 0; j < D; j++) s += W2[k * D + j] * Wr[j];
    g_w2r[k] = s;
    if (k == 0) {
        float c = 0.f;
        for (int j = 0; j < D; j++) c += b2[j] * Wr[j];
        g_c = c + br[0];
    }
}

// ------------------------- GEMM + q epilogue --------------------------------
// Per row: u = rin[row]*acc_row; y = relu(u @ W1 + b1);
//          q[row] = rout[row] * dot(y, w2r).
// 32 rows/block, 256 threads, thread = 4 rows x 2 cols.
__global__ void k_gemm_q(const float* __restrict__ W1,
                         const float* __restrict__ b1, int n) {
    __shared__ float Ws[D * D];
    __shared__ float Us[32][D];
    __shared__ float w2s[D];
    __shared__ float b1s[D];
    const int t = threadIdx.x;

#pragma unroll
    for (int i = 0; i < (D * D) / 256; i++)
        Ws[t + 256 * i] = W1[t + 256 * i];
    if (t < D) { w2s[t] = g_w2r[t]; b1s[t] = b1[t]; }

    const int row0 = blockIdx.x * 32;
    for (int idx = t; idx < 32 * D; idx += 256) {
        int r = idx >> 6, k = idx & (D - 1);
        int row = row0 + r;
        Us[r][k] = (row < n) ? g_acc[(size_t)row * D + k] * g_rin[row] : 0.f;
    }
    __syncthreads();

    const int tx = t & 31, ty = t >> 5;
    float acc[4][2] = {{0.f,0.f},{0.f,0.f},{0.f,0.f},{0.f,0.f}};
#pragma unroll
    for (int k = 0; k < D; k++) {
        float w0 = Ws[k * D + tx];
        float w1 = Ws[k * D + tx + 32];
#pragma unroll
        for (int r = 0; r < 4; r++) {
            float u = Us[ty * 4 + r][k];
            acc[r][0] = fmaf(u, w0, acc[r][0]);
            acc[r][1] = fmaf(u, w1, acc[r][1]);
        }
    }

#pragma unroll
    for (int r = 0; r < 4; r++) {
        int row = row0 + ty * 4 + r;
        float y0 = fmaxf(acc[r][0] + b1s[tx], 0.f);
        float y1 = fmaxf(acc[r][1] + b1s[tx + 32], 0.f);
        float p = y0 * w2s[tx] + y1 * w2s[tx + 32];
#pragma unroll
        for (int o = 16; o; o >>= 1) p += __shfl_xor_sync(0xffffffffu, p, o);
        if (tx == 0 && row < n) g_q[row] = p * g_rout[row];
    }
}

// ------------------------- layer-2 scalar scatter ---------------------------

__global__ void k_init_out(float* __restrict__ out, int n) {
    int i = blockIdx.x * blockDim.x + threadIdx.x;
    if (i < n) out[i] = g_q[i];          // self-loop term
}

__global__ void k_scatter2(const int* __restrict__ src,
                           const int* __restrict__ dst,
                           float* __restrict__ out, int e, int n) {
    int t = blockIdx.x * blockDim.x + threadIdx.x;
    if (t >= e) return;
    int st = g_stride;
    int s = load_idx(src, t, st, n);
    int d = load_idx(dst, t, st, n);
    atomicAdd(&out[d], g_q[s]);
}

__global__ void k_finalize(float* __restrict__ out, int n) {
    int i = blockIdx.x * blockDim.x + threadIdx.x;
    if (i < n) out[i] = fmaf(out[i], g_rin[i], g_c);
}

// ------------------------------ launch --------------------------------------

extern "C" void kernel_launch(void* const* d_in, const int* in_sizes, int n_in,
                              void* d_out, int out_size) {
    const float* x   = (const float*)d_in[0];
    const int*   src = (const int*)d_in[1];
    const int*   dst = (const int*)d_in[2];
    const float* W1  = (const float*)d_in[3];
    const float* b1  = (const float*)d_in[4];
    const float* W2  = (const float*)d_in[5];
    const float* b2  = (const float*)d_in[6];
    const float* Wr  = (const float*)d_in[7];
    const float* br  = (const float*)d_in[8];
    float*       out = (float*)d_out;

    const int n = in_sizes[0] / D;
    const int e = in_sizes[1];

    k_detect<<<1, 256>>>((const unsigned*)d_in[1], e);
    k_deg_init<<<(n + 255) / 256, 256>>>(n);
    k_deg<<<(e + 255) / 256, 256>>>(src, dst, e, n);
    k_rsqrt<<<(n + 255) / 256, 256>>>(n);
    k_w2r<<<1, 64>>>(W2, b2, Wr, br);

    k_init_acc<<<(n * (D / 4) + 255) / 256, 256>>>((const float4*)x, n);
    {
        long long th = (long long)e * 16;
        k_scatter1<<<(int)((th + 255) / 256), 256>>>(x, src, dst, e, n);
    }
    k_gemm_q<<<(n + 31) / 32, 256>>>(W1, b1, n);

    k_init_out<<<(n + 255) / 256, 256>>>(out, n);
    k_scatter2<<<(e + 255) / 256, 256>>>(src, dst, out, e, n);
    k_finalize<<<(n + 255) / 256, 256>>>(out, n);
}

// round 7
// speedup vs baseline: 1.0361x; 1.0361x over previous
#include <cuda_runtime.h>
#include <stdint.h>
#include <stdlib.h>

// ---------------------------------------------------------------------------
// GCN 2-layer forward, N=100k, E=1.6M, d=64. CSR-gather formulation:
//   counts -> scan -> csr (dst-major, atomic cursor fill)
//   agg+GEMM+q fused: per 64-row tile, gather u = rin*(x_self*rout + sum x[s]*rout[s])
//                     from CSR into smem, then y=relu(u@W1+b1), q=rout*(y . W2@Wr)
//   out = rin*(q_self + sum_in q[s]) + (b2.Wr + br)   (CSR gather, no atomics)
// No vector atomics anywhere. Total device-global scratch ~8.5MB.
// ---------------------------------------------------------------------------

#define MAXN 100352
#define MAXE 1605632
#define D 64

__device__ int   g_cnt_out[MAXN];
__device__ int   g_cnt_in[MAXN];
__device__ int   g_row_ptr[MAXN + 1];
__device__ int   g_cursor[MAXN];
__device__ int   g_csr_src[MAXE];
__device__ float g_q[MAXN];
__device__ int   g_partials[1024];
__device__ int   g_stride_;          // 1 = int32 indices; 2 = int64 (low word)

__attribute__((constructor))
static void _eager_modules() { setenv("CUDA_MODULE_LOADING", "EAGER", 1); }

__device__ __forceinline__ int load_idx(const int* p, int t, int st, int n) {
    int v = p[(size_t)t * st];
    return min(max(v, 0), n - 1);
}

// ---------------- zero counts + detect index dtype (block 0) ---------------

__global__ void k_zero_detect(const unsigned* __restrict__ srcw, int e, int n) {
    int i = blockIdx.x * 256 + threadIdx.x;
    if (i < n) { g_cnt_out[i] = 0; g_cnt_in[i] = 0; }
    if (blockIdx.x == 0) {
        __shared__ int nz;
        if (threadIdx.x == 0) nz = 0;
        __syncthreads();
        int words = min(e, 4096);
        for (int j = threadIdx.x; j < words; j += 256)
            if (srcw[2 * j + 1] != 0u) { nz = 1; break; }
        __syncthreads();
        if (threadIdx.x == 0) g_stride_ = nz ? 1 : 2;
    }
}

// ------------------------------- degrees -----------------------------------

__global__ void k_deg(const int* __restrict__ src, const int* __restrict__ dst,
                      int e, int n) {
    int t = blockIdx.x * blockDim.x + threadIdx.x;
    if (t >= e) return;
    int st = g_stride_;
    atomicAdd(&g_cnt_out[load_idx(src, t, st, n)], 1);
    atomicAdd(&g_cnt_in[load_idx(dst, t, st, n)], 1);
}

// ----------------------- 3-kernel exclusive scan ---------------------------

__global__ void k_scan_partial(int n) {
    __shared__ int sh[256];
    int i = blockIdx.x * 256 + threadIdx.x;
    int v = (i < n) ? g_cnt_in[i] : 0;
    sh[threadIdx.x] = v;
    __syncthreads();
    for (int off = 128; off; off >>= 1) {
        if (threadIdx.x < off) sh[threadIdx.x] += sh[threadIdx.x + off];
        __syncthreads();
    }
    if (threadIdx.x == 0) g_partials[blockIdx.x] = sh[0];
}

__global__ void k_scan_block(int nb) {
    __shared__ int sh[1024];
    int t = threadIdx.x;                      // 1024 threads
    int v = (t < nb) ? g_partials[t] : 0;
    sh[t] = v;
    __syncthreads();
    for (int off = 1; off < 1024; off <<= 1) {
        int add = (t >= off) ? sh[t - off] : 0;
        __syncthreads();
        sh[t] += add;
        __syncthreads();
    }
    if (t < nb) g_partials[t] = sh[t] - v;    // exclusive
}

__global__ void k_scan_final(int n) {
    __shared__ int sh[256];
    int t = threadIdx.x;
    int i = blockIdx.x * 256 + t;
    int v = (i < n) ? g_cnt_in[i] : 0;
    sh[t] = v;
    __syncthreads();
    for (int off = 1; off < 256; off <<= 1) {
        int add = (t >= off) ? sh[t - off] : 0;
        __syncthreads();
        sh[t] += add;
        __syncthreads();
    }
    int excl = sh[t] - v + g_partials[blockIdx.x];
    if (i < n) {
        g_row_ptr[i] = excl;
        g_cursor[i]  = excl;
        if (i == n - 1) g_row_ptr[n] = excl + v;
    }
}

// ------------------------------- CSR fill ----------------------------------

__global__ void k_fill(const int* __restrict__ src, const int* __restrict__ dst,
                       int e, int n) {
    int t = blockIdx.x * blockDim.x + threadIdx.x;
    if (t >= e) return;
    int st = g_stride_;
    int s = load_idx(src, t, st, n);
    int d = load_idx(dst, t, st, n);
    int pos = atomicAdd(&g_cursor[d], 1);
    g_csr_src[pos] = s;
}

// ---------------- fused aggregation + GEMM + q epilogue --------------------
// Block = 64 rows, 256 threads (8 warps x 8 rows each).
// Gather: half-warp per edge stream, lane covers one float4 feature chunk.

__global__ __launch_bounds__(256)
void k_agg_gemm_q(const float* __restrict__ x, const float* __restrict__ W1,
                  const float* __restrict__ b1, const float* __restrict__ W2,
                  const float* __restrict__ Wr, int n) {
    __shared__ float Ws[D * D];      // 16 KB
    __shared__ float Us[64][D];      // 16 KB
    __shared__ float w2s[D], b1s[D];
    const int t = threadIdx.x;

    if (t < D) {
        float s = 0.f;
#pragma unroll
        for (int j = 0; j < D; j++) s += W2[t * D + j] * Wr[j];
        w2s[t] = s;
        b1s[t] = b1[t];
    }
#pragma unroll
    for (int i = 0; i < (D * D) / 256; i++)
        Ws[t + 256 * i] = W1[t + 256 * i];

    const int row0 = blockIdx.x * 64;
    const int wy = t >> 5, lane = t & 31;
    const int half = lane >> 4, cc = lane & 15;
    const float4* x4 = (const float4*)x;

    for (int r = 0; r < 8; r++) {
        int row = row0 + wy * 8 + r;
        float4 a = make_float4(0.f, 0.f, 0.f, 0.f);
        float4 b = make_float4(0.f, 0.f, 0.f, 0.f);
        if (row < n) {
            if (half == 0) {                       // self-loop term
                float rt = rsqrtf(1.0f + (float)g_cnt_out[row]);
                float4 v = x4[row * 16 + cc];
                a.x = v.x * rt; a.y = v.y * rt; a.z = v.z * rt; a.w = v.w * rt;
            }
            int start = g_row_ptr[row], end = g_row_ptr[row + 1];
            int j = start + half;
            for (; j + 2 < end; j += 4) {          // 2 edges in flight per half
                int s0 = g_csr_src[j], s1 = g_csr_src[j + 2];
                float r0 = rsqrtf(1.0f + (float)g_cnt_out[s0]);
                float r1 = rsqrtf(1.0f + (float)g_cnt_out[s1]);
                float4 v0 = x4[s0 * 16 + cc];
                float4 v1 = x4[s1 * 16 + cc];
                a.x = fmaf(v0.x, r0, a.x); a.y = fmaf(v0.y, r0, a.y);
                a.z = fmaf(v0.z, r0, a.z); a.w = fmaf(v0.w, r0, a.w);
                b.x = fmaf(v1.x, r1, b.x); b.y = fmaf(v1.y, r1, b.y);
                b.z = fmaf(v1.z, r1, b.z); b.w = fmaf(v1.w, r1, b.w);
            }
            for (; j < end; j += 2) {
                int s0 = g_csr_src[j];
                float r0 = rsqrtf(1.0f + (float)g_cnt_out[s0]);
                float4 v0 = x4[s0 * 16 + cc];
                a.x = fmaf(v0.x, r0, a.x); a.y = fmaf(v0.y, r0, a.y);
                a.z = fmaf(v0.z, r0, a.z); a.w = fmaf(v0.w, r0, a.w);
            }
            a.x += b.x; a.y += b.y; a.z += b.z; a.w += b.w;
        }
        // combine the two halves
        a.x += __shfl_xor_sync(0xffffffffu, a.x, 16);
        a.y += __shfl_xor_sync(0xffffffffu, a.y, 16);
        a.z += __shfl_xor_sync(0xffffffffu, a.z, 16);
        a.w += __shfl_xor_sync(0xffffffffu, a.w, 16);
        if (half == 0) {
            float rin = (row < n) ? rsqrtf(1.0f + (float)g_cnt_in[row]) : 0.f;
            a.x *= rin; a.y *= rin; a.z *= rin; a.w *= rin;
            *(float4*)&Us[wy * 8 + r][cc * 4] = a;
        }
    }
    __syncthreads();

    // GEMM: thread = 8 rows x 2 cols
    const int tx = lane;
    float acc[8][2];
#pragma unroll
    for (int r = 0; r < 8; r++) { acc[r][0] = 0.f; acc[r][1] = 0.f; }
#pragma unroll
    for (int k = 0; k < D; k++) {
        float w0 = Ws[k * D + tx];
        float w1 = Ws[k * D + tx + 32];
#pragma unroll
        for (int r = 0; r < 8; r++) {
            float u = Us[wy * 8 + r][k];           // warp broadcast
            acc[r][0] = fmaf(u, w0, acc[r][0]);
            acc[r][1] = fmaf(u, w1, acc[r][1]);
        }
    }
#pragma unroll
    for (int r = 0; r < 8; r++) {
        int row = row0 + wy * 8 + r;
        float y0 = fmaxf(acc[r][0] + b1s[tx], 0.f);
        float y1 = fmaxf(acc[r][1] + b1s[tx + 32], 0.f);
        float p = y0 * w2s[tx] + y1 * w2s[tx + 32];
#pragma unroll
        for (int o = 16; o; o >>= 1) p += __shfl_xor_sync(0xffffffffu, p, o);
        if (tx == 0 && row < n)
            g_q[row] = p * rsqrtf(1.0f + (float)g_cnt_out[row]);
    }
}

// -------------------- layer-2 gather + finalize (fused) ---------------------
// warp per node: out = rin*(q_self + sum_in q[s]) + (b2.Wr + br)

__global__ void k_out(const float* __restrict__ b2, const float* __restrict__ Wr,
                      const float* __restrict__ br, float* __restrict__ out, int n) {
    __shared__ float c_sh;
    if (threadIdx.x == 0) {
        float c = 0.f;
        for (int j = 0; j < D; j++) c += b2[j] * Wr[j];
        c_sh = c + br[0];
    }
    __syncthreads();
    int node = blockIdx.x * 8 + (threadIdx.x >> 5);
    int lane = threadIdx.x & 31;
    if (node >= n) return;
    int start = g_row_ptr[node], end = g_row_ptr[node + 1];
    float s = 0.f;
    for (int j = start + lane; j < end; j += 32)
        s += g_q[g_csr_src[j]];
#pragma unroll
    for (int o = 16; o; o >>= 1) s += __shfl_xor_sync(0xffffffffu, s, o);
    if (lane == 0) {
        float rin = rsqrtf(1.0f + (float)g_cnt_in[node]);
        out[node] = fmaf(s + g_q[node], rin, c_sh);
    }
}

// ------------------------------- launch -------------------------------------

extern "C" void kernel_launch(void* const* d_in, const int* in_sizes, int n_in,
                              void* d_out, int out_size) {
    const float* x   = (const float*)d_in[0];
    const int*   src = (const int*)d_in[1];
    const int*   dst = (const int*)d_in[2];
    const float* W1  = (const float*)d_in[3];
    const float* b1  = (const float*)d_in[4];
    const float* W2  = (const float*)d_in[5];
    const float* b2  = (const float*)d_in[6];
    const float* Wr  = (const float*)d_in[7];
    const float* br  = (const float*)d_in[8];
    float*       out = (float*)d_out;

    const int n = in_sizes[0] / D;
    const int e = in_sizes[1];
    const int nb = (n + 255) / 256;

    k_zero_detect<<<nb, 256>>>((const unsigned*)d_in[1], e, n);
    k_deg<<<(e + 255) / 256, 256>>>(src, dst, e, n);
    k_scan_partial<<<nb, 256>>>(n);
    k_scan_block<<<1, 1024>>>(nb);
    k_scan_final<<<nb, 256>>>(n);
    k_fill<<<(e + 255) / 256, 256>>>(src, dst, e, n);

    k_agg_gemm_q<<<(n + 63) / 64, 256>>>(x, W1, b1, W2, Wr, n);
    k_out<<<(n + 7) / 8, 256>>>(b2, Wr, br, out, n);
}

// round 8
// speedup vs baseline: 1.0879x; 1.0500x over previous
#include <cuda_runtime.h>
#include <stdint.h>
#include <stdlib.h>

// ---------------------------------------------------------------------------
// GCN 2-layer forward, N=100k, E=1.6M, d=64. CSR-gather formulation:
//   counts -> scan -> csr fill {src, rsqrt(1+deg_out[src])} (dst-major)
//   agg+GEMM+q fused: per 64-row tile, gather u = rin*(x_self*rout + sum x[s]*scale)
//                     from CSR into smem, then y=relu(u@W1+b1), q=rout*(y . W2@Wr)
//   out = rin*(q_self + sum_in q[s]) + (b2.Wr + br)   (CSR gather, no atomics)
// Scale folded into CSR: 1 rsqrt per edge (not 16), no per-edge cnt loads.
// Total device-global scratch ~15MB.
// ---------------------------------------------------------------------------

#define MAXN 100352
#define MAXE 1605632
#define D 64

__device__ int   g_cnt_out[MAXN];
__device__ int   g_cnt_in[MAXN];
__device__ int   g_row_ptr[MAXN + 1];
__device__ int   g_cursor[MAXN];
__device__ int2  g_csr[MAXE];        // {src, float bits of rsqrt(1+deg_out[src])}
__device__ float g_q[MAXN];
__device__ int   g_partials[1024];
__device__ int   g_stride_;          // 1 = int32 indices; 2 = int64 (low word)

__attribute__((constructor))
static void _eager_modules() { setenv("CUDA_MODULE_LOADING", "EAGER", 1); }

__device__ __forceinline__ int load_idx(const int* p, int t, int st, int n) {
    int v = p[(size_t)t * st];
    return min(max(v, 0), n - 1);
}

// ---------------- zero counts + detect index dtype (block 0) ---------------

__global__ void k_zero_detect(const unsigned* __restrict__ srcw, int e, int n) {
    int i = blockIdx.x * 256 + threadIdx.x;
    if (i < n) { g_cnt_out[i] = 0; g_cnt_in[i] = 0; }
    if (blockIdx.x == 0) {
        __shared__ int nz;
        if (threadIdx.x == 0) nz = 0;
        __syncthreads();
        int words = min(e, 4096);
        for (int j = threadIdx.x; j < words; j += 256)
            if (srcw[2 * j + 1] != 0u) { nz = 1; break; }
        __syncthreads();
        if (threadIdx.x == 0) g_stride_ = nz ? 1 : 2;
    }
}

// ------------------------------- degrees -----------------------------------

__global__ void k_deg(const int* __restrict__ src, const int* __restrict__ dst,
                      int e, int n) {
    int t = blockIdx.x * blockDim.x + threadIdx.x;
    if (t >= e) return;
    int st = g_stride_;
    atomicAdd(&g_cnt_out[load_idx(src, t, st, n)], 1);
    atomicAdd(&g_cnt_in[load_idx(dst, t, st, n)], 1);
}

// ----------------------- 3-kernel exclusive scan ---------------------------

__global__ void k_scan_partial(int n) {
    __shared__ int sh[256];
    int i = blockIdx.x * 256 + threadIdx.x;
    int v = (i < n) ? g_cnt_in[i] : 0;
    sh[threadIdx.x] = v;
    __syncthreads();
    for (int off = 128; off; off >>= 1) {
        if (threadIdx.x < off) sh[threadIdx.x] += sh[threadIdx.x + off];
        __syncthreads();
    }
    if (threadIdx.x == 0) g_partials[blockIdx.x] = sh[0];
}

// 512 threads, shuffle-based exclusive scan of up to 512 partials.
__global__ void k_scan_block(int nb) {
    __shared__ int ws[16];
    int t = threadIdx.x, lane = t & 31, wid = t >> 5;
    int v = (t < nb) ? g_partials[t] : 0;
    int s = v;
#pragma unroll
    for (int o = 1; o < 32; o <<= 1) {
        int y = __shfl_up_sync(0xffffffffu, s, o);
        if (lane >= o) s += y;
    }
    if (lane == 31) ws[wid] = s;
    __syncthreads();
    if (wid == 0) {
        int w = (lane < 16) ? ws[lane] : 0;
#pragma unroll
        for (int o = 1; o < 16; o <<= 1) {
            int y = __shfl_up_sync(0xffffffffu, w, o);
            if (lane >= o) w += y;
        }
        if (lane < 16) ws[lane] = w;
    }
    __syncthreads();
    int base = (wid > 0) ? ws[wid - 1] : 0;
    if (t < nb) g_partials[t] = base + s - v;   // exclusive
}

__global__ void k_scan_final(int n) {
    __shared__ int sh[256];
    int t = threadIdx.x;
    int i = blockIdx.x * 256 + t;
    int v = (i < n) ? g_cnt_in[i] : 0;
    sh[t] = v;
    __syncthreads();
    for (int off = 1; off < 256; off <<= 1) {
        int add = (t >= off) ? sh[t - off] : 0;
        __syncthreads();
        sh[t] += add;
        __syncthreads();
    }
    int excl = sh[t] - v + g_partials[blockIdx.x];
    if (i < n) {
        g_row_ptr[i] = excl;
        g_cursor[i]  = excl;
        if (i == n - 1) g_row_ptr[n] = excl + v;
    }
}

// ------------------------------- CSR fill ----------------------------------
// Stores {src, rsqrt(1+deg_out[src])}: one MUFU + one cnt load PER EDGE.

__global__ void k_fill(const int* __restrict__ src, const int* __restrict__ dst,
                       int e, int n) {
    int t = blockIdx.x * blockDim.x + threadIdx.x;
    if (t >= e) return;
    int st = g_stride_;
    int s = load_idx(src, t, st, n);
    int d = load_idx(dst, t, st, n);
    float sc = rsqrtf(1.0f + (float)g_cnt_out[s]);
    int pos = atomicAdd(&g_cursor[d], 1);
    g_csr[pos] = make_int2(s, __float_as_int(sc));
}

// ---------------- fused aggregation + GEMM + q epilogue --------------------
// Block = 64 rows, 256 threads (8 warps x 8 rows each).
// Gather: half-warp per edge stream, lane covers one float4 feature chunk.

__global__ __launch_bounds__(256)
void k_agg_gemm_q(const float* __restrict__ x, const float* __restrict__ W1,
                  const float* __restrict__ b1, const float* __restrict__ W2,
                  const float* __restrict__ Wr, int n) {
    __shared__ float Ws[D * D];      // 16 KB
    __shared__ float Us[64][D];      // 16 KB
    __shared__ float w2s[D], b1s[D];
    const int t = threadIdx.x;

    if (t < D) {
        float s = 0.f;
#pragma unroll
        for (int j = 0; j < D; j++) s += W2[t * D + j] * Wr[j];
        w2s[t] = s;
        b1s[t] = b1[t];
    }
#pragma unroll
    for (int i = 0; i < (D * D) / 256; i++)
        Ws[t + 256 * i] = W1[t + 256 * i];

    const int row0 = blockIdx.x * 64;
    const int wy = t >> 5, lane = t & 31;
    const int half = lane >> 4, cc = lane & 15;
    const float4* x4 = (const float4*)x;

    for (int r = 0; r < 8; r++) {
        int row = row0 + wy * 8 + r;
        float4 a = make_float4(0.f, 0.f, 0.f, 0.f);
        float4 b = make_float4(0.f, 0.f, 0.f, 0.f);
        if (row < n) {
            if (half == 0) {                       // self-loop term
                float rt = rsqrtf(1.0f + (float)g_cnt_out[row]);
                float4 v = x4[row * 16 + cc];
                a.x = v.x * rt; a.y = v.y * rt; a.z = v.z * rt; a.w = v.w * rt;
            }
            int start = g_row_ptr[row], end = g_row_ptr[row + 1];
            int j = start + half;
            for (; j + 2 < end; j += 4) {          // 2 edges in flight per half
                int2 e0 = g_csr[j], e1 = g_csr[j + 2];
                float r0 = __int_as_float(e0.y);
                float r1 = __int_as_float(e1.y);
                float4 v0 = x4[e0.x * 16 + cc];
                float4 v1 = x4[e1.x * 16 + cc];
                a.x = fmaf(v0.x, r0, a.x); a.y = fmaf(v0.y, r0, a.y);
                a.z = fmaf(v0.z, r0, a.z); a.w = fmaf(v0.w, r0, a.w);
                b.x = fmaf(v1.x, r1, b.x); b.y = fmaf(v1.y, r1, b.y);
                b.z = fmaf(v1.z, r1, b.z); b.w = fmaf(v1.w, r1, b.w);
            }
            for (; j < end; j += 2) {
                int2 e0 = g_csr[j];
                float r0 = __int_as_float(e0.y);
                float4 v0 = x4[e0.x * 16 + cc];
                a.x = fmaf(v0.x, r0, a.x); a.y = fmaf(v0.y, r0, a.y);
                a.z = fmaf(v0.z, r0, a.z); a.w = fmaf(v0.w, r0, a.w);
            }
            a.x += b.x; a.y += b.y; a.z += b.z; a.w += b.w;
        }
        // combine the two halves
        a.x += __shfl_xor_sync(0xffffffffu, a.x, 16);
        a.y += __shfl_xor_sync(0xffffffffu, a.y, 16);
        a.z += __shfl_xor_sync(0xffffffffu, a.z, 16);
        a.w += __shfl_xor_sync(0xffffffffu, a.w, 16);
        if (half == 0) {
            float rin = (row < n) ? rsqrtf(1.0f + (float)g_cnt_in[row]) : 0.f;
            a.x *= rin; a.y *= rin; a.z *= rin; a.w *= rin;
            *(float4*)&Us[wy * 8 + r][cc * 4] = a;
        }
    }
    __syncthreads();

    // GEMM: thread = 8 rows x 2 cols
    const int tx = lane;
    float acc[8][2];
#pragma unroll
    for (int r = 0; r < 8; r++) { acc[r][0] = 0.f; acc[r][1] = 0.f; }
#pragma unroll
    for (int k = 0; k < D; k++) {
        float w0 = Ws[k * D + tx];
        float w1 = Ws[k * D + tx + 32];
#pragma unroll
        for (int r = 0; r < 8; r++) {
            float u = Us[wy * 8 + r][k];           // warp broadcast
            acc[r][0] = fmaf(u, w0, acc[r][0]);
            acc[r][1] = fmaf(u, w1, acc[r][1]);
        }
    }
#pragma unroll
    for (int r = 0; r < 8; r++) {
        int row = row0 + wy * 8 + r;
        float y0 = fmaxf(acc[r][0] + b1s[tx], 0.f);
        float y1 = fmaxf(acc[r][1] + b1s[tx + 32], 0.f);
        float p = y0 * w2s[tx] + y1 * w2s[tx + 32];
#pragma unroll
        for (int o = 16; o; o >>= 1) p += __shfl_xor_sync(0xffffffffu, p, o);
        if (tx == 0 && row < n)
            g_q[row] = p * rsqrtf(1.0f + (float)g_cnt_out[row]);
    }
}

// -------------------- layer-2 gather + finalize (fused) ---------------------
// 2 nodes per warp (16 lanes each): out = rin*(q_self + sum_in q[s]) + c

__global__ void k_out(const float* __restrict__ b2, const float* __restrict__ Wr,
                      const float* __restrict__ br, float* __restrict__ out, int n) {
    __shared__ float c_sh;
    if (threadIdx.x == 0) {
        float c = 0.f;
        for (int j = 0; j < D; j++) c += b2[j] * Wr[j];
        c_sh = c + br[0];
    }
    __syncthreads();
    int half_id = (blockIdx.x * blockDim.x + threadIdx.x) >> 4;
    int node = half_id;
    int lane = threadIdx.x & 15;
    if (node >= n) return;
    int start = g_row_ptr[node], end = g_row_ptr[node + 1];
    float s = 0.f;
    for (int j = start + lane; j < end; j += 16)
        s += g_q[g_csr[j].x];
#pragma unroll
    for (int o = 8; o; o >>= 1) s += __shfl_xor_sync(0xffffffffu, s, o, 16);
    if (lane == 0) {
        float rin = rsqrtf(1.0f + (float)g_cnt_in[node]);
        out[node] = fmaf(s + g_q[node], rin, c_sh);
    }
}

// ------------------------------- launch -------------------------------------

extern "C" void kernel_launch(void* const* d_in, const int* in_sizes, int n_in,
                              void* d_out, int out_size) {
    const float* x   = (const float*)d_in[0];
    const int*   src = (const int*)d_in[1];
    const int*   dst = (const int*)d_in[2];
    const float* W1  = (const float*)d_in[3];
    const float* b1  = (const float*)d_in[4];
    const float* W2  = (const float*)d_in[5];
    const float* b2  = (const float*)d_in[6];
    const float* Wr  = (const float*)d_in[7];
    const float* br  = (const float*)d_in[8];
    float*       out = (float*)d_out;

    const int n = in_sizes[0] / D;
    const int e = in_sizes[1];
    const int nb = (n + 255) / 256;

    k_zero_detect<<<nb, 256>>>((const unsigned*)d_in[1], e, n);
    k_deg<<<(e + 255) / 256, 256>>>(src, dst, e, n);
    k_scan_partial<<<nb, 256>>>(n);
    k_scan_block<<<1, 512>>>(nb);
    k_scan_final<<<nb, 256>>>(n);
    k_fill<<<(e + 255) / 256, 256>>>(src, dst, e, n);

    k_agg_gemm_q<<<(n + 63) / 64, 256>>>(x, W1, b1, W2, Wr, n);
    k_out<<<((n * 16) + 255) / 256, 256>>>(b2, Wr, br, out, n);
}

// round 9
// speedup vs baseline: 1.0954x; 1.0069x over previous
#include <cuda_runtime.h>
#include <stdint.h>
#include <stdlib.h>

// ---------------------------------------------------------------------------
// GCN 2-layer forward, N=100k, E=1.6M, d=64. CSR-gather formulation:
//   counts -> scan -> csr fill {src, rsqrt(1+deg_out[src])} (dst-major)
//   agg+GEMM+q fused: per 64-row tile, gather u = rin*(x_self*rout + sum x[s]*sc)
//                     then y=relu(u@W1+b1), q=rout*(y . W2@Wr)
//   out = rin*(q_self + sum_in q[s]) + (b2.Wr + br)
// Gather uses ONE coalesced csr load per 32 edges + register shuffles, so
// x-row loads are independent (high MLP) instead of chained behind csr loads.
// ---------------------------------------------------------------------------

#define MAXN 100352
#define MAXE 1605632
#define D 64
#define FULL 0xffffffffu

__device__ int   g_cnt_out[MAXN];
__device__ int   g_cnt_in[MAXN];
__device__ int   g_row_ptr[MAXN + 1];
__device__ int   g_cursor[MAXN];
__device__ int2  g_csr[MAXE];        // {src, float bits of rsqrt(1+deg_out[src])}
__device__ float g_q[MAXN];
__device__ int   g_partials[1024];
__device__ int   g_stride_;          // 1 = int32 indices; 2 = int64 (low word)

__attribute__((constructor))
static void _eager_modules() { setenv("CUDA_MODULE_LOADING", "EAGER", 1); }

__device__ __forceinline__ int load_idx(const int* p, int t, int st, int n) {
    int v = p[(size_t)t * st];
    return min(max(v, 0), n - 1);
}

// ---------------- zero counts + detect index dtype (block 0) ---------------

__global__ void k_zero_detect(const unsigned* __restrict__ srcw, int e, int n) {
    int i = blockIdx.x * 256 + threadIdx.x;
    if (i < n) { g_cnt_out[i] = 0; g_cnt_in[i] = 0; }
    if (blockIdx.x == 0) {
        __shared__ int nz;
        if (threadIdx.x == 0) nz = 0;
        __syncthreads();
        int words = min(e, 4096);
        for (int j = threadIdx.x; j < words; j += 256)
            if (srcw[2 * j + 1] != 0u) { nz = 1; break; }
        __syncthreads();
        if (threadIdx.x == 0) g_stride_ = nz ? 1 : 2;
    }
}

// ------------------------------- degrees -----------------------------------

__global__ void k_deg(const int* __restrict__ src, const int* __restrict__ dst,
                      int e, int n) {
    int t = blockIdx.x * blockDim.x + threadIdx.x;
    if (t >= e) return;
    int st = g_stride_;
    atomicAdd(&g_cnt_out[load_idx(src, t, st, n)], 1);
    atomicAdd(&g_cnt_in[load_idx(dst, t, st, n)], 1);
}

// ----------------------- 3-kernel exclusive scan ---------------------------

__global__ void k_scan_partial(int n) {
    __shared__ int sh[256];
    int i = blockIdx.x * 256 + threadIdx.x;
    int v = (i < n) ? g_cnt_in[i] : 0;
    sh[threadIdx.x] = v;
    __syncthreads();
    for (int off = 128; off; off >>= 1) {
        if (threadIdx.x < off) sh[threadIdx.x] += sh[threadIdx.x + off];
        __syncthreads();
    }
    if (threadIdx.x == 0) g_partials[blockIdx.x] = sh[0];
}

__global__ void k_scan_block(int nb) {
    __shared__ int ws[16];
    int t = threadIdx.x, lane = t & 31, wid = t >> 5;
    int v = (t < nb) ? g_partials[t] : 0;
    int s = v;
#pragma unroll
    for (int o = 1; o < 32; o <<= 1) {
        int y = __shfl_up_sync(FULL, s, o);
        if (lane >= o) s += y;
    }
    if (lane == 31) ws[wid] = s;
    __syncthreads();
    if (wid == 0) {
        int w = (lane < 16) ? ws[lane] : 0;
#pragma unroll
        for (int o = 1; o < 16; o <<= 1) {
            int y = __shfl_up_sync(FULL, w, o);
            if (lane >= o) w += y;
        }
        if (lane < 16) ws[lane] = w;
    }
    __syncthreads();
    int base = (wid > 0) ? ws[wid - 1] : 0;
    if (t < nb) g_partials[t] = base + s - v;   // exclusive
}

__global__ void k_scan_final(int n) {
    __shared__ int sh[256];
    int t = threadIdx.x;
    int i = blockIdx.x * 256 + t;
    int v = (i < n) ? g_cnt_in[i] : 0;
    sh[t] = v;
    __syncthreads();
    for (int off = 1; off < 256; off <<= 1) {
        int add = (t >= off) ? sh[t - off] : 0;
        __syncthreads();
        sh[t] += add;
        __syncthreads();
    }
    int excl = sh[t] - v + g_partials[blockIdx.x];
    if (i < n) {
        g_row_ptr[i] = excl;
        g_cursor[i]  = excl;
        if (i == n - 1) g_row_ptr[n] = excl + v;
    }
}

// ------------------------------- CSR fill ----------------------------------

__global__ void k_fill(const int* __restrict__ src, const int* __restrict__ dst,
                       int e, int n) {
    int t = blockIdx.x * blockDim.x + threadIdx.x;
    if (t >= e) return;
    int st = g_stride_;
    int s = load_idx(src, t, st, n);
    int d = load_idx(dst, t, st, n);
    float sc = rsqrtf(1.0f + (float)g_cnt_out[s]);
    int pos = atomicAdd(&g_cursor[d], 1);
    g_csr[pos] = make_int2(s, __float_as_int(sc));
}

// ---------------- fused aggregation + GEMM + q epilogue --------------------
// Block = 64 rows, 256 threads (8 warps x 8 rows each).
// Gather: 1 coalesced csr load per 32 edges; shuffles distribute entries;
// halves of the warp process adjacent edges (cc = feature chunk).

__global__ __launch_bounds__(256)
void k_agg_gemm_q(const float* __restrict__ x, const float* __restrict__ W1,
                  const float* __restrict__ b1, const float* __restrict__ W2,
                  const float* __restrict__ Wr, int n) {
    __shared__ float Ws[D * D];      // 16 KB
    __shared__ float Us[64][D];      // 16 KB
    __shared__ float w2s[D], b1s[D];
    const int t = threadIdx.x;

    if (t < D) {
        float s = 0.f;
#pragma unroll
        for (int j = 0; j < D; j++) s += W2[t * D + j] * Wr[j];
        w2s[t] = s;
        b1s[t] = b1[t];
    }
#pragma unroll
    for (int i = 0; i < (D * D) / 256; i++)
        Ws[t + 256 * i] = W1[t + 256 * i];

    const int row0 = blockIdx.x * 64;
    const int wy = t >> 5, lane = t & 31;
    const int half = lane >> 4, cc = lane & 15;
    const float4* x4 = (const float4*)x;

    for (int r = 0; r < 8; r++) {
        int row = row0 + wy * 8 + r;
        bool valid = row < n;
        int start = 0, end = 0;
        if (valid) { start = g_row_ptr[row]; end = g_row_ptr[row + 1]; }

        float4 a = make_float4(0.f, 0.f, 0.f, 0.f);
        float4 b = make_float4(0.f, 0.f, 0.f, 0.f);

        if (valid && half == 0) {                  // self-loop term
            float rt = rsqrtf(1.0f + (float)g_cnt_out[row]);
            float4 v = x4[row * 16 + cc];
            a.x = v.x * rt; a.y = v.y * rt; a.z = v.z * rt; a.w = v.w * rt;
        }

        for (int base = start; base < end; base += 32) {
            int cnt = min(32, end - base);
            // one coalesced csr load covers up to 32 edges
            int2 my = g_csr[base + min(lane, cnt - 1)];
            int k = 0;
            for (; k + 8 <= cnt; k += 8) {
                int   s0 = __shfl_sync(FULL, my.x, k + half);
                float c0 = __int_as_float(__shfl_sync(FULL, my.y, k + half));
                int   s1 = __shfl_sync(FULL, my.x, k + 2 + half);
                float c1 = __int_as_float(__shfl_sync(FULL, my.y, k + 2 + half));
                int   s2 = __shfl_sync(FULL, my.x, k + 4 + half);
                float c2 = __int_as_float(__shfl_sync(FULL, my.y, k + 4 + half));
                int   s3 = __shfl_sync(FULL, my.x, k + 6 + half);
                float c3 = __int_as_float(__shfl_sync(FULL, my.y, k + 6 + half));
                float4 v0 = x4[s0 * 16 + cc];
                float4 v1 = x4[s1 * 16 + cc];
                float4 v2 = x4[s2 * 16 + cc];
                float4 v3 = x4[s3 * 16 + cc];
                a.x = fmaf(v0.x, c0, a.x); a.y = fmaf(v0.y, c0, a.y);
                a.z = fmaf(v0.z, c0, a.z); a.w = fmaf(v0.w, c0, a.w);
                b.x = fmaf(v1.x, c1, b.x); b.y = fmaf(v1.y, c1, b.y);
                b.z = fmaf(v1.z, c1, b.z); b.w = fmaf(v1.w, c1, b.w);
                a.x = fmaf(v2.x, c2, a.x); a.y = fmaf(v2.y, c2, a.y);
                a.z = fmaf(v2.z, c2, a.z); a.w = fmaf(v2.w, c2, a.w);
                b.x = fmaf(v3.x, c3, b.x); b.y = fmaf(v3.y, c3, b.y);
                b.z = fmaf(v3.z, c3, b.z); b.w = fmaf(v3.w, c3, b.w);
            }
            for (; k < cnt; k += 2) {              // tail: shuffles uniform, load predicated
                int kk = min(k + half, cnt - 1);
                int   s0 = __shfl_sync(FULL, my.x, kk);
                float c0 = __int_as_float(__shfl_sync(FULL, my.y, kk));
                if (k + half < cnt) {
                    float4 v0 = x4[s0 * 16 + cc];
                    a.x = fmaf(v0.x, c0, a.x); a.y = fmaf(v0.y, c0, a.y);
                    a.z = fmaf(v0.z, c0, a.z); a.w = fmaf(v0.w, c0, a.w);
                }
            }
        }
        a.x += b.x; a.y += b.y; a.z += b.z; a.w += b.w;
        // combine halves
        a.x += __shfl_xor_sync(FULL, a.x, 16);
        a.y += __shfl_xor_sync(FULL, a.y, 16);
        a.z += __shfl_xor_sync(FULL, a.z, 16);
        a.w += __shfl_xor_sync(FULL, a.w, 16);
        if (half == 0) {
            float rin = valid ? rsqrtf(1.0f + (float)g_cnt_in[row]) : 0.f;
            a.x *= rin; a.y *= rin; a.z *= rin; a.w *= rin;
            *(float4*)&Us[wy * 8 + r][cc * 4] = a;
        }
    }
    __syncthreads();

    // GEMM: thread = 8 rows x 2 cols
    const int tx = lane;
    float acc[8][2];
#pragma unroll
    for (int r = 0; r < 8; r++) { acc[r][0] = 0.f; acc[r][1] = 0.f; }
#pragma unroll
    for (int k = 0; k < D; k++) {
        float w0 = Ws[k * D + tx];
        float w1 = Ws[k * D + tx + 32];
#pragma unroll
        for (int r = 0; r < 8; r++) {
            float u = Us[wy * 8 + r][k];           // warp broadcast
            acc[r][0] = fmaf(u, w0, acc[r][0]);
            acc[r][1] = fmaf(u, w1, acc[r][1]);
        }
    }
#pragma unroll
    for (int r = 0; r < 8; r++) {
        int row = row0 + wy * 8 + r;
        float y0 = fmaxf(acc[r][0] + b1s[tx], 0.f);
        float y1 = fmaxf(acc[r][1] + b1s[tx + 32], 0.f);
        float p = y0 * w2s[tx] + y1 * w2s[tx + 32];
#pragma unroll
        for (int o = 16; o; o >>= 1) p += __shfl_xor_sync(FULL, p, o);
        if (tx == 0 && row < n)
            g_q[row] = p * rsqrtf(1.0f + (float)g_cnt_out[row]);
    }
}

// -------------------- layer-2 gather + finalize (fused) ---------------------
// 2 nodes per warp (16 lanes each): out = rin*(q_self + sum_in q[s]) + c

__global__ void k_out(const float* __restrict__ b2, const float* __restrict__ Wr,
                      const float* __restrict__ br, float* __restrict__ out, int n) {
    __shared__ float c_sh;
    if (threadIdx.x == 0) {
        float c = 0.f;
        for (int j = 0; j < D; j++) c += b2[j] * Wr[j];
        c_sh = c + br[0];
    }
    __syncthreads();
    int node = (blockIdx.x * blockDim.x + threadIdx.x) >> 4;
    int lane = threadIdx.x & 15;
    if (node >= n) return;
    int start = g_row_ptr[node], end = g_row_ptr[node + 1];
    float s = 0.f;
    for (int j = start + lane; j < end; j += 16)
        s += g_q[g_csr[j].x];
#pragma unroll
    for (int o = 8; o; o >>= 1) s += __shfl_xor_sync(FULL, s, o, 16);
    if (lane == 0) {
        float rin = rsqrtf(1.0f + (float)g_cnt_in[node]);
        out[node] = fmaf(s + g_q[node], rin, c_sh);
    }
}

// ------------------------------- launch -------------------------------------

extern "C" void kernel_launch(void* const* d_in, const int* in_sizes, int n_in,
                              void* d_out, int out_size) {
    const float* x   = (const float*)d_in[0];
    const int*   src = (const int*)d_in[1];
    const int*   dst = (const int*)d_in[2];
    const float* W1  = (const float*)d_in[3];
    const float* b1  = (const float*)d_in[4];
    const float* W2  = (const float*)d_in[5];
    const float* b2  = (const float*)d_in[6];
    const float* Wr  = (const float*)d_in[7];
    const float* br  = (const float*)d_in[8];
    float*       out = (float*)d_out;

    const int n = in_sizes[0] / D;
    const int e = in_sizes[1];
    const int nb = (n + 255) / 256;

    k_zero_detect<<<nb, 256>>>((const unsigned*)d_in[1], e, n);
    k_deg<<<(e + 255) / 256, 256>>>(src, dst, e, n);
    k_scan_partial<<<nb, 256>>>(n);
    k_scan_block<<<1, 512>>>(nb);
    k_scan_final<<<nb, 256>>>(n);
    k_fill<<<(e + 255) / 256, 256>>>(src, dst, e, n);

    k_agg_gemm_q<<<(n + 63) / 64, 256>>>(x, W1, b1, W2, Wr, n);
    k_out<<<((n * 16) + 255) / 256, 256>>>(b2, Wr, br, out, n);
}